// round 7
// baseline (speedup 1.0000x reference)
#include <cuda_runtime.h>
#include <cstdint>
#include <math.h>

// Fused 3x3 conv via warp-level tf32 tensor-core MMA with exact 3xTF32
// splitting (fp32-class accuracy) + LIF scan in registers + flag-and-fix.
// (Resubmission of round-5 kernel: previous bench was an infra failure,
// so the 3xTF32 theory is still awaiting its first measurement.)
//
// x: [T=8, B=16, Cin=64, 64, 64] f32   w: [64, 64, 3, 3] f32
// out: spikes [8, 16, 64, 64, 64] f32
//
// Implicit GEMM per CTA tile (128 px x 64 co), k = tap*64 + ci (576 total).
// smem holds RAW fp32; Dekker truncation split (hi = bits&0xffffe000,
// lo = x - hi, exact) in registers; acc += Ah*Bh + Al*Bh + Ah*Bl.
// Bank-conflict-free pitches: input ci-pitch 184 words, weight k-pitch 72.

#define TT 8
#define BB 16

#define W_PITCH 72
#define CI_PITCH 184
#define SM_W_WORDS (576 * W_PITCH)                 // 41472 words
#define SMEM_WORDS (SM_W_WORDS + 64 * CI_PITCH)    // + 11776 = 53248
#define SMEM_BYTES (SMEM_WORDS * 4)                // 212992 B

#define FLAG_CAP 131072
#define FLAG_DELTA 4e-5f
#define HIMASK 0xffffe000u

__device__ int g_cnt;    // zeroed at module load; reset by fix_kernel
__device__ int g_done;
__device__ int g_idx[FLAG_CAP];

__device__ __forceinline__ void mma8(float* c, const uint32_t* a,
                                     uint32_t b0, uint32_t b1) {
    asm volatile(
        "mma.sync.aligned.m16n8k8.row.col.f32.tf32.tf32.f32 "
        "{%0,%1,%2,%3}, {%4,%5,%6,%7}, {%8,%9}, {%0,%1,%2,%3};"
        : "+f"(c[0]), "+f"(c[1]), "+f"(c[2]), "+f"(c[3])
        : "r"(a[0]), "r"(a[1]), "r"(a[2]), "r"(a[3]), "r"(b0), "r"(b1));
}
__device__ __forceinline__ void push_flag(int enc) {
    int i = atomicAdd(&g_cnt, 1);
    if (i < FLAG_CAP) g_idx[i] = enc;
}

__global__ __launch_bounds__(256, 1)
void snn_conv_lif_kernel(const float* __restrict__ x,
                         const float* __restrict__ w,
                         float* __restrict__ out)
{
    extern __shared__ float smem[];
    float* wsm = smem;                    // [k=576][co, pitch 72] raw f32
    float* ins = smem + SM_W_WORDS;       // [ci=64, pitch 184][10y][18x] raw f32

    const int tid  = threadIdx.x;
    const int wid  = tid >> 5;
    const int lane = tid & 31;
    const int gid  = lane >> 2;          // 0..7
    const int tig  = lane & 3;           // 0..3
    const int b    = blockIdx.x >> 5;
    const int tile = blockIdx.x & 31;
    const int ty0  = (tile >> 2) * 8;    // tile row origin (8 rows)
    const int tx0  = (tile & 3) * 16;    // tile col origin (16 cols)

    const int warpM = wid & 3;           // M chunk of 32 px  (2 y-rows)
    const int warpN = wid >> 2;          // N chunk of 32 co

    // ---- stage weights: w[co][ci][ky][kx] -> wsm[(tap*64+ci)*72 + co] ----
    for (int idx = tid; idx < 64 * 64 * 9; idx += 256) {
        int co  = idx / 576;
        int r   = idx % 576;
        int ci  = r / 9;
        int tap = r % 9;
        wsm[(tap * 64 + ci) * W_PITCH + co] = w[idx];
    }

    float v[32];
    #pragma unroll
    for (int i = 0; i < 32; ++i) v[i] = 0.0f;

    for (int t = 0; t < TT; ++t) {
        __syncthreads();   // prev compute done (fences weight staging at t=0)

        // ---- stage input tile (raw fp32, zero-padded halo) ----
        const float* xt = x + (size_t)(t * BB + b) * (64 * 64 * 64);
        for (int m = tid; m < 64 * 10 * 18; m += 256) {
            int txi = m % 18;
            int rem = m / 18;
            int tyi = rem % 10;
            int ci  = rem / 10;
            int gy = ty0 + tyi - 1;
            int gx = tx0 + txi - 1;
            float val = 0.0f;
            if ((unsigned)gy < 64u && (unsigned)gx < 64u)
                val = xt[ci * 4096 + gy * 64 + gx];
            ins[ci * CI_PITCH + tyi * 18 + txi] = val;
        }
        __syncthreads();

        // ---- implicit GEMM, 3xTF32 split: acc[mt*16 + nt*4 + r] ----
        float acc[32];
        #pragma unroll
        for (int i = 0; i < 32; ++i) acc[i] = 0.0f;

        #pragma unroll 1
        for (int tap = 0; tap < 9; ++tap) {
            const int ky = tap / 3, kx = tap % 3;
            const int aoff0 = (warpM * 2 + ky) * 18 + kx + gid; // mt=0 row base
            const int koff  = tap * 64;

            #pragma unroll 2
            for (int kb = 0; kb < 8; ++kb) {
                const int ci0 = kb * 8 + tig;
                // raw A fragments for mt=0,1, then exact truncation split
                uint32_t ah[2][4], al[2][4];
                #pragma unroll
                for (int mt = 0; mt < 2; ++mt) {
                    const int base = ci0 * CI_PITCH + aoff0 + mt * 18;
                    float ar[4];
                    ar[0] = ins[base];
                    ar[1] = ins[base + 8];
                    ar[2] = ins[base + 4 * CI_PITCH];
                    ar[3] = ins[base + 4 * CI_PITCH + 8];
                    #pragma unroll
                    for (int j = 0; j < 4; ++j) {
                        uint32_t h = __float_as_uint(ar[j]) & HIMASK;
                        ah[mt][j] = h;
                        al[mt][j] = __float_as_uint(ar[j] - __uint_as_float(h));
                    }
                }
                // B fragments (raw -> split) + 3 MMAs per (mt,nt)
                const int kk = (koff + ci0) * W_PITCH + warpN * 32 + gid;
                #pragma unroll
                for (int nt = 0; nt < 4; ++nt) {
                    float b0r = wsm[kk + nt * 8];
                    float b1r = wsm[kk + nt * 8 + 4 * W_PITCH];
                    uint32_t b0h = __float_as_uint(b0r) & HIMASK;
                    uint32_t b1h = __float_as_uint(b1r) & HIMASK;
                    uint32_t b0l = __float_as_uint(b0r - __uint_as_float(b0h));
                    uint32_t b1l = __float_as_uint(b1r - __uint_as_float(b1h));
                    mma8(&acc[nt * 4],      ah[0], b0h, b1h);
                    mma8(&acc[nt * 4],      al[0], b0h, b1h);
                    mma8(&acc[nt * 4],      ah[0], b0l, b1l);
                    mma8(&acc[16 + nt * 4], ah[1], b0h, b1h);
                    mma8(&acc[16 + nt * 4], al[1], b0h, b1h);
                    mma8(&acc[16 + nt * 4], ah[1], b0l, b1l);
                }
            }
        }

        // ---- LIF update + near-threshold flagging + spike store ----
        float* obase = out + (size_t)(t * BB + b) * (64 * 4096);
        #pragma unroll
        for (int mt = 0; mt < 2; ++mt) {
            const int yg = ty0 + warpM * 2 + mt;
            #pragma unroll
            for (int nt = 0; nt < 4; ++nt) {
                #pragma unroll
                for (int r = 0; r < 4; ++r) {
                    const int co = warpN * 32 + nt * 8 + 2 * tig + (r & 1);
                    const int xg = tx0 + gid + ((r & 2) ? 8 : 0);
                    const int vi = mt * 16 + nt * 4 + r;
                    float z = acc[vi];
                    float vv = v[vi];
                    vv = vv + (z - vv) * 0.5f;   // TAU=2, reference op order
                    if (fabsf(vv - 1.0f) < FLAG_DELTA)
                        push_flag((((b * 64 + co) * 64 + yg) * 64) + xg);
                    float s = (vv >= 1.0f) ? 1.0f : 0.0f;
                    v[vi] = (vv >= 1.0f) ? 0.0f : vv;
                    obase[(size_t)co * 4096 + yg * 64 + xg] = s;
                }
            }
        }
    }
}

// ---------------- flag-and-fix ----------------
// Warp-per-trajectory: exact fp64 conv (lane-split ci + shuffle reduce),
// round z to fp32, reference-identical fp32 LIF. Overwrites all T spikes.
// Last block resets g_cnt/g_done so the captured graph is replay-safe.
__global__ void fix_kernel(const float* __restrict__ x,
                           const float* __restrict__ w,
                           float* __restrict__ out)
{
    int n = g_cnt;
    if (n > FLAG_CAP) n = FLAG_CAP;
    const int lane = threadIdx.x & 31;
    const int wid  = (blockIdx.x * blockDim.x + threadIdx.x) >> 5;
    const int nw   = (gridDim.x * blockDim.x) >> 5;

    for (int i = wid; i < n; i += nw) {
        int e = g_idx[i];
        int xp = e & 63;
        int y  = (e >> 6) & 63;
        int co = (e >> 12) & 63;
        int b  = e >> 18;
        const float* wr = w + co * 576;
        const int ci0 = lane * 2;
        float v = 0.0f;
        for (int t = 0; t < TT; ++t) {
            const float* xt = x + (size_t)(t * BB + b) * (64 * 64 * 64);
            double z = 0.0;
            #pragma unroll
            for (int cc = 0; cc < 2; ++cc) {
                int ci = ci0 + cc;
                #pragma unroll
                for (int ky = 0; ky < 3; ++ky) {
                    int gy = y + ky - 1;
                    if ((unsigned)gy >= 64u) continue;
                    const float* xr = xt + ci * 4096 + gy * 64;
                    const float* wk = wr + ci * 9 + ky * 3;
                    #pragma unroll
                    for (int kx = 0; kx < 3; ++kx) {
                        int gx = xp + kx - 1;
                        if ((unsigned)gx >= 64u) continue;
                        z += (double)xr[gx] * (double)wk[kx];
                    }
                }
            }
            #pragma unroll
            for (int off = 16; off > 0; off >>= 1)
                z += __shfl_down_sync(0xffffffffu, z, off);
            if (lane == 0) {
                float zf = (float)z;
                v = v + (zf - v) * 0.5f;
                float s = (v >= 1.0f) ? 1.0f : 0.0f;
                v = (v >= 1.0f) ? 0.0f : v;
                out[((size_t)(t * BB + b) * 64 + co) * 4096 + y * 64 + xp] = s;
            }
        }
    }

    __syncthreads();
    if (threadIdx.x == 0) {
        __threadfence();
        int d = atomicAdd(&g_done, 1);
        if (d == (int)gridDim.x - 1) {
            g_cnt = 0;
            g_done = 0;
            __threadfence();
        }
    }
}

extern "C" void kernel_launch(void* const* d_in, const int* in_sizes, int n_in,
                              void* d_out, int out_size) {
    const float* x  = (const float*)d_in[0];
    const float* w  = (const float*)d_in[1];
    float* out      = (float*)d_out;
    cudaFuncSetAttribute(snn_conv_lif_kernel,
                         cudaFuncAttributeMaxDynamicSharedMemorySize, SMEM_BYTES);
    snn_conv_lif_kernel<<<512, 256, SMEM_BYTES>>>(x, w, out);
    fix_kernel<<<256, 256>>>(x, w, out);
}

// round 9
// speedup vs baseline: 1.4714x; 1.4714x over previous
#include <cuda_runtime.h>
#include <cuda_fp16.h>
#include <cstdint>
#include <math.h>

// Fused 3x3 conv via fp16 m16n8k16 tensor-core MMA with exact 2-term Dekker
// split (3 products: AhBh + AlBh + AhBl, fp32 accumulate -> fp32-class z)
// + LIF scan in registers + flag-and-fix.
// (Resubmission: rounds 6 and 8 were broker/container infra failures; this
// kernel is still awaiting its first measurement.)
//
// x: [T=8, B=16, Cin=64, 64, 64] f32   w: [64, 64, 3, 3] f32
// out: spikes [8, 16, 64, 64, 64] f32
//
// hi/lo halves produced ONCE at smem staging (separate planes, ci-contiguous).
// Pitches of 36 words give lane-address = 4*gid+tig (a 32-bank bijection) for
// every A and B fragment load -> conflict-free.

#define TT 8
#define BB 16

// word (4B) offsets in dynamic smem
#define WPLANE_WORDS (576 * 36)           // [tap*64+co][ci/2] f16x2, pitch 36
#define INPLANE_WORDS (180 * 36)          // [y*18+x][ci/2] f16x2, pitch 36
#define SM_WH 0
#define SM_WL WPLANE_WORDS
#define SM_INH (2 * WPLANE_WORDS)
#define SM_INL (2 * WPLANE_WORDS + INPLANE_WORDS)
#define SMEM_WORDS (2 * WPLANE_WORDS + 2 * INPLANE_WORDS)
#define SMEM_BYTES (SMEM_WORDS * 4)       // 217,728 B

#define FLAG_CAP 131072
#define FLAG_DELTA 4e-5f

__device__ int g_cnt;    // zeroed at module load; reset by fix_kernel
__device__ int g_done;
__device__ int g_idx[FLAG_CAP];

__device__ __forceinline__ void mma16(float* c, const uint32_t* a,
                                      uint32_t b0, uint32_t b1) {
    asm volatile(
        "mma.sync.aligned.m16n8k16.row.col.f32.f16.f16.f32 "
        "{%0,%1,%2,%3}, {%4,%5,%6,%7}, {%8,%9}, {%0,%1,%2,%3};"
        : "+f"(c[0]), "+f"(c[1]), "+f"(c[2]), "+f"(c[3])
        : "r"(a[0]), "r"(a[1]), "r"(a[2]), "r"(a[3]), "r"(b0), "r"(b1));
}
__device__ __forceinline__ void push_flag(int enc) {
    int i = atomicAdd(&g_cnt, 1);
    if (i < FLAG_CAP) g_idx[i] = enc;
}

__global__ __launch_bounds__(256, 1)
void snn_conv_lif_kernel(const float* __restrict__ x,
                         const float* __restrict__ w,
                         float* __restrict__ out)
{
    extern __shared__ uint32_t smem[];
    uint32_t* whU  = smem + SM_WH;
    uint32_t* wlU  = smem + SM_WL;
    uint32_t* inhU = smem + SM_INH;
    uint32_t* inlU = smem + SM_INL;
    __half* whH  = reinterpret_cast<__half*>(whU);
    __half* wlH  = reinterpret_cast<__half*>(wlU);
    __half* inhH = reinterpret_cast<__half*>(inhU);
    __half* inlH = reinterpret_cast<__half*>(inlU);

    const int tid  = threadIdx.x;
    const int wid  = tid >> 5;
    const int lane = tid & 31;
    const int gid  = lane >> 2;          // 0..7
    const int tig  = lane & 3;           // 0..3
    const int b    = blockIdx.x >> 5;
    const int tile = blockIdx.x & 31;
    const int ty0  = (tile >> 2) * 8;    // tile row origin (8 rows)
    const int tx0  = (tile & 3) * 16;    // tile col origin (16 cols)

    const int warpM = wid & 3;           // M chunk of 32 px  (2 y-rows)
    const int warpN = wid >> 2;          // N chunk of 32 co

    // ---- stage weights: split to hi/lo half-planes [tap*64+co][ci] ----
    for (int idx = tid; idx < 64 * 64 * 9; idx += 256) {
        int co  = idx / 576;
        int r   = idx % 576;
        int ci  = r / 9;
        int tap = r % 9;
        float f = w[idx];
        __half h = __float2half_rn(f);
        __half l = __float2half_rn(f - __half2float(h));
        int hidx = (tap * 64 + co) * 72 + ci;   // half-index (pitch 72 halves)
        whH[hidx] = h;
        wlH[hidx] = l;
    }

    float v[32];
    #pragma unroll
    for (int i = 0; i < 32; ++i) v[i] = 0.0f;

    for (int t = 0; t < TT; ++t) {
        __syncthreads();   // prev compute done (fences weight staging at t=0)

        // ---- stage input tile: split to hi/lo planes [y*18+x][ci] ----
        const float* xt = x + (size_t)(t * BB + b) * (64 * 64 * 64);
        for (int m = tid; m < 64 * 10 * 18; m += 256) {
            int txi = m % 18;
            int rem = m / 18;
            int tyi = rem % 10;
            int ci  = rem / 10;
            int gy = ty0 + tyi - 1;
            int gx = tx0 + txi - 1;
            float val = 0.0f;
            if ((unsigned)gy < 64u && (unsigned)gx < 64u)
                val = xt[ci * 4096 + gy * 64 + gx];
            __half h = __float2half_rn(val);
            __half l = __float2half_rn(val - __half2float(h));
            int hidx = (tyi * 18 + txi) * 72 + ci;  // half-index
            inhH[hidx] = h;
            inlH[hidx] = l;
        }
        __syncthreads();

        // ---- implicit GEMM, fp16 split x3 products: acc[mt*16+nt*4+r] ----
        float acc[32];
        #pragma unroll
        for (int i = 0; i < 32; ++i) acc[i] = 0.0f;

        #pragma unroll 1
        for (int tap = 0; tap < 9; ++tap) {
            const int ky = tap / 3, kx = tap % 3;

            #pragma unroll
            for (int kb = 0; kb < 4; ++kb) {       // 16 ci per k-tile
                // A fragments (hi & lo) for mt = 0,1
                uint32_t ah[2][4], al[2][4];
                #pragma unroll
                for (int mt = 0; mt < 2; ++mt) {
                    const int pix = (warpM * 2 + mt + ky) * 18 + kx + gid;
                    const int pa  = pix * 36 + kb * 8 + tig;
                    const int pb  = pa + 8 * 36;   // pixel x + 8
                    ah[mt][0] = inhU[pa];
                    ah[mt][1] = inhU[pb];
                    ah[mt][2] = inhU[pa + 4];
                    ah[mt][3] = inhU[pb + 4];
                    al[mt][0] = inlU[pa];
                    al[mt][1] = inlU[pb];
                    al[mt][2] = inlU[pa + 4];
                    al[mt][3] = inlU[pb + 4];
                }
                // B fragments + 3 MMAs per (mt, nt)
                #pragma unroll
                for (int nt = 0; nt < 4; ++nt) {
                    const int co = warpN * 32 + nt * 8 + gid;
                    const int wi = (tap * 64 + co) * 36 + kb * 8 + tig;
                    uint32_t bh0 = whU[wi], bh1 = whU[wi + 4];
                    uint32_t bl0 = wlU[wi], bl1 = wlU[wi + 4];
                    mma16(&acc[nt * 4],      ah[0], bh0, bh1);
                    mma16(&acc[nt * 4],      al[0], bh0, bh1);
                    mma16(&acc[nt * 4],      ah[0], bl0, bl1);
                    mma16(&acc[16 + nt * 4], ah[1], bh0, bh1);
                    mma16(&acc[16 + nt * 4], al[1], bh0, bh1);
                    mma16(&acc[16 + nt * 4], ah[1], bl0, bl1);
                }
            }
        }

        // ---- LIF update + near-threshold flagging + spike store ----
        float* obase = out + (size_t)(t * BB + b) * (64 * 4096);
        #pragma unroll
        for (int mt = 0; mt < 2; ++mt) {
            const int yg = ty0 + warpM * 2 + mt;
            #pragma unroll
            for (int nt = 0; nt < 4; ++nt) {
                #pragma unroll
                for (int r = 0; r < 4; ++r) {
                    const int co = warpN * 32 + nt * 8 + 2 * tig + (r & 1);
                    const int xg = tx0 + gid + ((r & 2) ? 8 : 0);
                    const int vi = mt * 16 + nt * 4 + r;
                    float z = acc[vi];
                    float vv = v[vi];
                    vv = vv + (z - vv) * 0.5f;   // TAU=2, reference op order
                    if (fabsf(vv - 1.0f) < FLAG_DELTA)
                        push_flag((((b * 64 + co) * 64 + yg) * 64) + xg);
                    float s = (vv >= 1.0f) ? 1.0f : 0.0f;
                    v[vi] = (vv >= 1.0f) ? 0.0f : vv;
                    obase[(size_t)co * 4096 + yg * 64 + xg] = s;
                }
            }
        }
    }
}

// ---------------- flag-and-fix ----------------
// Warp-per-trajectory: exact fp64 conv (lane-split ci + shuffle reduce),
// round z to fp32, reference-identical fp32 LIF. Overwrites all T spikes.
// Last block resets g_cnt/g_done so the captured graph is replay-safe.
__global__ void fix_kernel(const float* __restrict__ x,
                           const float* __restrict__ w,
                           float* __restrict__ out)
{
    int n = g_cnt;
    if (n > FLAG_CAP) n = FLAG_CAP;
    const int lane = threadIdx.x & 31;
    const int wid  = (blockIdx.x * blockDim.x + threadIdx.x) >> 5;
    const int nw   = (gridDim.x * blockDim.x) >> 5;

    for (int i = wid; i < n; i += nw) {
        int e = g_idx[i];
        int xp = e & 63;
        int y  = (e >> 6) & 63;
        int co = (e >> 12) & 63;
        int b  = e >> 18;
        const float* wr = w + co * 576;
        const int ci0 = lane * 2;
        float v = 0.0f;
        for (int t = 0; t < TT; ++t) {
            const float* xt = x + (size_t)(t * BB + b) * (64 * 64 * 64);
            double z = 0.0;
            #pragma unroll
            for (int cc = 0; cc < 2; ++cc) {
                int ci = ci0 + cc;
                #pragma unroll
                for (int ky = 0; ky < 3; ++ky) {
                    int gy = y + ky - 1;
                    if ((unsigned)gy >= 64u) continue;
                    const float* xr = xt + ci * 4096 + gy * 64;
                    const float* wk = wr + ci * 9 + ky * 3;
                    #pragma unroll
                    for (int kx = 0; kx < 3; ++kx) {
                        int gx = xp + kx - 1;
                        if ((unsigned)gx >= 64u) continue;
                        z += (double)xr[gx] * (double)wk[kx];
                    }
                }
            }
            #pragma unroll
            for (int off = 16; off > 0; off >>= 1)
                z += __shfl_down_sync(0xffffffffu, z, off);
            if (lane == 0) {
                float zf = (float)z;
                v = v + (zf - v) * 0.5f;
                float s = (v >= 1.0f) ? 1.0f : 0.0f;
                v = (v >= 1.0f) ? 0.0f : v;
                out[((size_t)(t * BB + b) * 64 + co) * 4096 + y * 64 + xp] = s;
            }
        }
    }

    __syncthreads();
    if (threadIdx.x == 0) {
        __threadfence();
        int d = atomicAdd(&g_done, 1);
        if (d == (int)gridDim.x - 1) {
            g_cnt = 0;
            g_done = 0;
            __threadfence();
        }
    }
}

extern "C" void kernel_launch(void* const* d_in, const int* in_sizes, int n_in,
                              void* d_out, int out_size) {
    const float* x  = (const float*)d_in[0];
    const float* w  = (const float*)d_in[1];
    float* out      = (float*)d_out;
    cudaFuncSetAttribute(snn_conv_lif_kernel,
                         cudaFuncAttributeMaxDynamicSharedMemorySize, SMEM_BYTES);
    snn_conv_lif_kernel<<<512, 256, SMEM_BYTES>>>(x, w, out);
    fix_kernel<<<256, 256>>>(x, w, out);
}

// round 10
// speedup vs baseline: 1.5368x; 1.0444x over previous
#include <cuda_runtime.h>
#include <cuda_fp16.h>
#include <cstdint>
#include <math.h>

// Fused 3x3 conv via fp16 m16n8k16 MMA with exact Dekker split (3 products,
// fp32-class z) + LIF scan + flag-and-fix.
//
// Round-9 change: persistent grid of 148 CTAs x 1024 small units (4x16 px):
// weights staged once per CTA, wave-quantization waste 15.6% -> 1.2%.
//
// x: [T=8, B=16, Cin=64, 64, 64] f32   w: [64, 64, 3, 3] f32
// out: spikes [8, 16, 64, 64, 64] f32

#define TT 8
#define BB 16
#define NSM 148
#define NUNITS 1024          // 16 b x 64 tiles (16 y-groups x 4 x-groups)

// word (4B) offsets in dynamic smem
#define WPLANE_WORDS (576 * 36)           // [tap*64+co][ci/2] f16x2, pitch 36
#define INPLANE_WORDS (108 * 36)          // [y*18+x][ci/2], 6 rows x 18 cols
#define SM_WH 0
#define SM_WL WPLANE_WORDS
#define SM_INH (2 * WPLANE_WORDS)
#define SM_INL (2 * WPLANE_WORDS + INPLANE_WORDS)
#define SMEM_WORDS (2 * WPLANE_WORDS + 2 * INPLANE_WORDS)
#define SMEM_BYTES (SMEM_WORDS * 4)       // 196,992 B

#define FLAG_CAP 131072
#define FLAG_DELTA 4e-5f

__device__ int g_cnt;    // zeroed at module load; reset by fix_kernel
__device__ int g_done;
__device__ int g_idx[FLAG_CAP];

__device__ __forceinline__ void mma16(float* c, const uint32_t* a,
                                      uint32_t b0, uint32_t b1) {
    asm volatile(
        "mma.sync.aligned.m16n8k16.row.col.f32.f16.f16.f32 "
        "{%0,%1,%2,%3}, {%4,%5,%6,%7}, {%8,%9}, {%0,%1,%2,%3};"
        : "+f"(c[0]), "+f"(c[1]), "+f"(c[2]), "+f"(c[3])
        : "r"(a[0]), "r"(a[1]), "r"(a[2]), "r"(a[3]), "r"(b0), "r"(b1));
}
__device__ __forceinline__ void push_flag(int enc) {
    int i = atomicAdd(&g_cnt, 1);
    if (i < FLAG_CAP) g_idx[i] = enc;
}

__global__ __launch_bounds__(256, 1)
void snn_conv_lif_kernel(const float* __restrict__ x,
                         const float* __restrict__ w,
                         float* __restrict__ out)
{
    extern __shared__ uint32_t smem[];
    uint32_t* whU  = smem + SM_WH;
    uint32_t* wlU  = smem + SM_WL;
    uint32_t* inhU = smem + SM_INH;
    uint32_t* inlU = smem + SM_INL;
    __half* whH  = reinterpret_cast<__half*>(whU);
    __half* wlH  = reinterpret_cast<__half*>(wlU);
    __half* inhH = reinterpret_cast<__half*>(inhU);
    __half* inlH = reinterpret_cast<__half*>(inlU);

    const int tid  = threadIdx.x;
    const int wid  = tid >> 5;
    const int lane = tid & 31;
    const int gid  = lane >> 2;          // 0..7
    const int tig  = lane & 3;           // 0..3

    const int warpM = wid & 3;           // 1 y-row of 16 px
    const int warpN = wid >> 2;          // 32-co half

    // ---- stage weights ONCE: hi/lo half-planes [tap*64+co][ci] ----
    for (int idx = tid; idx < 64 * 64 * 9; idx += 256) {
        int co  = idx / 576;
        int r   = idx % 576;
        int ci  = r / 9;
        int tap = r % 9;
        float f = w[idx];
        __half h = __float2half_rn(f);
        __half l = __float2half_rn(f - __half2float(h));
        int hidx = (tap * 64 + co) * 72 + ci;   // pitch 72 halves
        whH[hidx] = h;
        wlH[hidx] = l;
    }

    // ---- persistent loop over work units ----
    for (int u = blockIdx.x; u < NUNITS; u += NSM) {
        const int b    = u >> 6;
        const int tile = u & 63;
        const int ty0  = (tile >> 2) * 4;    // 16 y-groups of 4 rows
        const int tx0  = (tile & 3) * 16;    // 4 x-groups of 16 cols

        float v[16];
        #pragma unroll
        for (int i = 0; i < 16; ++i) v[i] = 0.0f;

        for (int t = 0; t < TT; ++t) {
            __syncthreads();   // prev mma readers done (covers weights at t=0)

            // ---- stage input tile: 64ci x 6y x 18x, hi/lo planes ----
            const float* xt = x + (size_t)(t * BB + b) * (64 * 64 * 64);
            for (int i = tid; i < 64 * 108; i += 256) {
                int ci  = i / 108;
                int pix = i - ci * 108;
                int tyi = pix / 18;
                int txi = pix - tyi * 18;
                int gy = ty0 + tyi - 1;
                int gx = tx0 + txi - 1;
                float val = 0.0f;
                if ((unsigned)gy < 64u && (unsigned)gx < 64u)
                    val = xt[ci * 4096 + gy * 64 + gx];
                __half h = __float2half_rn(val);
                __half l = __float2half_rn(val - __half2float(h));
                int hidx = pix * 72 + ci;
                inhH[hidx] = h;
                inlH[hidx] = l;
            }
            __syncthreads();

            // ---- implicit GEMM, fp16 split x3: acc[nt*4 + r] ----
            float acc[16];
            #pragma unroll
            for (int i = 0; i < 16; ++i) acc[i] = 0.0f;

            #pragma unroll 1
            for (int tap = 0; tap < 9; ++tap) {
                const int ky = tap / 3, kx = tap % 3;

                #pragma unroll
                for (int kb = 0; kb < 4; ++kb) {       // 16 ci per k-tile
                    // A fragments (hi & lo): rows = px gid / gid+8
                    const int pix = (warpM + ky) * 18 + kx + gid;
                    const int pa  = pix * 36 + kb * 8 + tig;
                    const int pb  = pa + 8 * 36;       // pixel x + 8
                    uint32_t ah[4], al[4];
                    ah[0] = inhU[pa];
                    ah[1] = inhU[pb];
                    ah[2] = inhU[pa + 4];
                    ah[3] = inhU[pb + 4];
                    al[0] = inlU[pa];
                    al[1] = inlU[pb];
                    al[2] = inlU[pa + 4];
                    al[3] = inlU[pb + 4];
                    // B fragments + 3 MMAs per nt
                    #pragma unroll
                    for (int nt = 0; nt < 4; ++nt) {
                        const int co = warpN * 32 + nt * 8 + gid;
                        const int wi = (tap * 64 + co) * 36 + kb * 8 + tig;
                        uint32_t bh0 = whU[wi], bh1 = whU[wi + 4];
                        uint32_t bl0 = wlU[wi], bl1 = wlU[wi + 4];
                        mma16(&acc[nt * 4], ah, bh0, bh1);
                        mma16(&acc[nt * 4], al, bh0, bh1);
                        mma16(&acc[nt * 4], ah, bl0, bl1);
                    }
                }
            }

            // ---- LIF update + near-threshold flagging + spike store ----
            float* obase = out + (size_t)(t * BB + b) * (64 * 4096);
            const int yg = ty0 + warpM;
            #pragma unroll
            for (int nt = 0; nt < 4; ++nt) {
                #pragma unroll
                for (int r = 0; r < 4; ++r) {
                    const int co = warpN * 32 + nt * 8 + 2 * tig + (r & 1);
                    const int xg = tx0 + gid + ((r & 2) ? 8 : 0);
                    const int vi = nt * 4 + r;
                    float z = acc[vi];
                    float vv = v[vi];
                    vv = vv + (z - vv) * 0.5f;   // TAU=2, reference op order
                    if (fabsf(vv - 1.0f) < FLAG_DELTA)
                        push_flag((((b * 64 + co) * 64 + yg) * 64) + xg);
                    float s = (vv >= 1.0f) ? 1.0f : 0.0f;
                    v[vi] = (vv >= 1.0f) ? 0.0f : vv;
                    obase[(size_t)co * 4096 + yg * 64 + xg] = s;
                }
            }
        }
    }
}

// ---------------- flag-and-fix ----------------
// Warp-per-trajectory: exact fp64 conv (lane-split ci + shuffle reduce),
// round z to fp32, reference-identical fp32 LIF. Overwrites all T spikes.
// Last block resets g_cnt/g_done so the captured graph is replay-safe.
__global__ void fix_kernel(const float* __restrict__ x,
                           const float* __restrict__ w,
                           float* __restrict__ out)
{
    int n = g_cnt;
    if (n > FLAG_CAP) n = FLAG_CAP;
    const int lane = threadIdx.x & 31;
    const int wid  = (blockIdx.x * blockDim.x + threadIdx.x) >> 5;
    const int nw   = (gridDim.x * blockDim.x) >> 5;

    for (int i = wid; i < n; i += nw) {
        int e = g_idx[i];
        int xp = e & 63;
        int y  = (e >> 6) & 63;
        int co = (e >> 12) & 63;
        int b  = e >> 18;
        const float* wr = w + co * 576;
        const int ci0 = lane * 2;
        float v = 0.0f;
        for (int t = 0; t < TT; ++t) {
            const float* xt = x + (size_t)(t * BB + b) * (64 * 64 * 64);
            double z = 0.0;
            #pragma unroll
            for (int cc = 0; cc < 2; ++cc) {
                int ci = ci0 + cc;
                #pragma unroll
                for (int ky = 0; ky < 3; ++ky) {
                    int gy = y + ky - 1;
                    if ((unsigned)gy >= 64u) continue;
                    const float* xr = xt + ci * 4096 + gy * 64;
                    const float* wk = wr + ci * 9 + ky * 3;
                    #pragma unroll
                    for (int kx = 0; kx < 3; ++kx) {
                        int gx = xp + kx - 1;
                        if ((unsigned)gx >= 64u) continue;
                        z += (double)xr[gx] * (double)wk[kx];
                    }
                }
            }
            #pragma unroll
            for (int off = 16; off > 0; off >>= 1)
                z += __shfl_down_sync(0xffffffffu, z, off);
            if (lane == 0) {
                float zf = (float)z;
                v = v + (zf - v) * 0.5f;
                float s = (v >= 1.0f) ? 1.0f : 0.0f;
                v = (v >= 1.0f) ? 0.0f : v;
                out[((size_t)(t * BB + b) * 64 + co) * 4096 + y * 64 + xp] = s;
            }
        }
    }

    __syncthreads();
    if (threadIdx.x == 0) {
        __threadfence();
        int d = atomicAdd(&g_done, 1);
        if (d == (int)gridDim.x - 1) {
            g_cnt = 0;
            g_done = 0;
            __threadfence();
        }
    }
}

extern "C" void kernel_launch(void* const* d_in, const int* in_sizes, int n_in,
                              void* d_out, int out_size) {
    const float* x  = (const float*)d_in[0];
    const float* w  = (const float*)d_in[1];
    float* out      = (float*)d_out;
    cudaFuncSetAttribute(snn_conv_lif_kernel,
                         cudaFuncAttributeMaxDynamicSharedMemorySize, SMEM_BYTES);
    snn_conv_lif_kernel<<<NSM, 256, SMEM_BYTES>>>(x, w, out);
    fix_kernel<<<256, 256>>>(x, w, out);
}

// round 11
// speedup vs baseline: 2.1834x; 1.4208x over previous
#include <cuda_runtime.h>
#include <cuda_fp16.h>
#include <cstdint>
#include <math.h>

// Fused 3x3 conv via fp16 m16n8k16 MMA with exact Dekker split (3 products,
// fp32-class z) + LIF scan + flag-and-fix.
//
// Round-10 change: software-pipelined input staging. Each thread prefetches
// its 27 input floats for timestep t+1 into registers BEFORE the timestep-t
// MMA loop, hiding LDG latency under tensor-core work; after the post-MMA
// sync only the cheap convert+STS phase is exposed.
//
// x: [T=8, B=16, Cin=64, 64, 64] f32   w: [64, 64, 3, 3] f32
// out: spikes [8, 16, 64, 64, 64] f32

#define TT 8
#define BB 16
#define NSM 148
#define NUNITS 1024          // 16 b x 64 tiles (16 y-groups x 4 x-groups)
#define PFN 27               // 64*108 / 256 prefetch elements per thread

// word (4B) offsets in dynamic smem
#define WPLANE_WORDS (576 * 36)           // [tap*64+co][ci/2] f16x2, pitch 36
#define INPLANE_WORDS (108 * 36)          // [y*18+x][ci/2], 6 rows x 18 cols
#define SM_WH 0
#define SM_WL WPLANE_WORDS
#define SM_INH (2 * WPLANE_WORDS)
#define SM_INL (2 * WPLANE_WORDS + INPLANE_WORDS)
#define SMEM_WORDS (2 * WPLANE_WORDS + 2 * INPLANE_WORDS)
#define SMEM_BYTES (SMEM_WORDS * 4)       // 196,992 B

#define FLAG_CAP 131072
#define FLAG_DELTA 4e-5f

__device__ int g_cnt;    // zeroed at module load; reset by fix_kernel
__device__ int g_done;
__device__ int g_idx[FLAG_CAP];

__device__ __forceinline__ void mma16(float* c, const uint32_t* a,
                                      uint32_t b0, uint32_t b1) {
    asm volatile(
        "mma.sync.aligned.m16n8k16.row.col.f32.f16.f16.f32 "
        "{%0,%1,%2,%3}, {%4,%5,%6,%7}, {%8,%9}, {%0,%1,%2,%3};"
        : "+f"(c[0]), "+f"(c[1]), "+f"(c[2]), "+f"(c[3])
        : "r"(a[0]), "r"(a[1]), "r"(a[2]), "r"(a[3]), "r"(b0), "r"(b1));
}
__device__ __forceinline__ void push_flag(int enc) {
    int i = atomicAdd(&g_cnt, 1);
    if (i < FLAG_CAP) g_idx[i] = enc;
}

__global__ __launch_bounds__(256, 1)
void snn_conv_lif_kernel(const float* __restrict__ x,
                         const float* __restrict__ w,
                         float* __restrict__ out)
{
    extern __shared__ uint32_t smem[];
    uint32_t* whU  = smem + SM_WH;
    uint32_t* wlU  = smem + SM_WL;
    uint32_t* inhU = smem + SM_INH;
    uint32_t* inlU = smem + SM_INL;
    __half* whH  = reinterpret_cast<__half*>(whU);
    __half* wlH  = reinterpret_cast<__half*>(wlU);
    __half* inhH = reinterpret_cast<__half*>(inhU);
    __half* inlH = reinterpret_cast<__half*>(inlU);

    const int tid  = threadIdx.x;
    const int wid  = tid >> 5;
    const int lane = tid & 31;
    const int gid  = lane >> 2;          // 0..7
    const int tig  = lane & 3;           // 0..3

    const int warpM = wid & 3;           // 1 y-row of 16 px
    const int warpN = wid >> 2;          // 32-co half

    // ---- stage weights ONCE: hi/lo half-planes [tap*64+co][ci] ----
    for (int idx = tid; idx < 64 * 64 * 9; idx += 256) {
        int co  = idx / 576;
        int r   = idx % 576;
        int ci  = r / 9;
        int tap = r % 9;
        float f = w[idx];
        __half h = __float2half_rn(f);
        __half l = __float2half_rn(f - __half2float(h));
        int hidx = (tap * 64 + co) * 72 + ci;   // pitch 72 halves
        whH[hidx] = h;
        wlH[hidx] = l;
    }

    // ---- persistent loop over work units ----
    for (int u = blockIdx.x; u < NUNITS; u += NSM) {
        const int b    = u >> 6;
        const int tile = u & 63;
        const int ty0  = (tile >> 2) * 4;    // 16 y-groups of 4 rows
        const int tx0  = (tile & 3) * 16;    // 4 x-groups of 16 cols

        float v[16];
        #pragma unroll
        for (int i = 0; i < 16; ++i) v[i] = 0.0f;

        // ---- direct stage for t=0 (also fences weights on first unit) ----
        {
            const float* xt = x + (size_t)b * (64 * 64 * 64);
            #pragma unroll
            for (int k = 0; k < PFN; ++k) {
                int i   = tid + k * 256;
                int ci  = i / 108;
                int pix = i - ci * 108;
                int tyi = pix / 18;
                int txi = pix - tyi * 18;
                int gy = ty0 + tyi - 1;
                int gx = tx0 + txi - 1;
                float val = 0.0f;
                if ((unsigned)gy < 64u && (unsigned)gx < 64u)
                    val = xt[ci * 4096 + gy * 64 + gx];
                __half h = __float2half_rn(val);
                __half l = __float2half_rn(val - __half2float(h));
                inhH[pix * 72 + ci] = h;
                inlH[pix * 72 + ci] = l;
            }
        }
        __syncthreads();

        for (int t = 0; t < TT; ++t) {
            // ---- prefetch NEXT timestep's inputs into registers ----
            float pf[PFN];
            if (t < TT - 1) {
                const float* xn = x + (size_t)((t + 1) * BB + b) * (64 * 64 * 64);
                #pragma unroll
                for (int k = 0; k < PFN; ++k) {
                    int i   = tid + k * 256;
                    int ci  = i / 108;
                    int pix = i - ci * 108;
                    int tyi = pix / 18;
                    int txi = pix - tyi * 18;
                    int gy = ty0 + tyi - 1;
                    int gx = tx0 + txi - 1;
                    float val = 0.0f;
                    if ((unsigned)gy < 64u && (unsigned)gx < 64u)
                        val = xn[ci * 4096 + gy * 64 + gx];
                    pf[k] = val;
                }
            }

            // ---- implicit GEMM, fp16 split x3: acc[nt*4 + r] ----
            float acc[16];
            #pragma unroll
            for (int i = 0; i < 16; ++i) acc[i] = 0.0f;

            #pragma unroll 1
            for (int tap = 0; tap < 9; ++tap) {
                const int ky = tap / 3, kx = tap % 3;

                #pragma unroll
                for (int kb = 0; kb < 4; ++kb) {       // 16 ci per k-tile
                    const int pix = (warpM + ky) * 18 + kx + gid;
                    const int pa  = pix * 36 + kb * 8 + tig;
                    const int pb  = pa + 8 * 36;       // pixel x + 8
                    uint32_t ah[4], al[4];
                    ah[0] = inhU[pa];
                    ah[1] = inhU[pb];
                    ah[2] = inhU[pa + 4];
                    ah[3] = inhU[pb + 4];
                    al[0] = inlU[pa];
                    al[1] = inlU[pb];
                    al[2] = inlU[pa + 4];
                    al[3] = inlU[pb + 4];
                    #pragma unroll
                    for (int nt = 0; nt < 4; ++nt) {
                        const int co = warpN * 32 + nt * 8 + gid;
                        const int wi = (tap * 64 + co) * 36 + kb * 8 + tig;
                        uint32_t bh0 = whU[wi], bh1 = whU[wi + 4];
                        uint32_t bl0 = wlU[wi], bl1 = wlU[wi + 4];
                        mma16(&acc[nt * 4], ah, bh0, bh1);
                        mma16(&acc[nt * 4], al, bh0, bh1);
                        mma16(&acc[nt * 4], ah, bl0, bl1);
                    }
                }
            }

            // ---- LIF update + near-threshold flagging + spike store ----
            float* obase = out + (size_t)(t * BB + b) * (64 * 4096);
            const int yg = ty0 + warpM;
            #pragma unroll
            for (int nt = 0; nt < 4; ++nt) {
                #pragma unroll
                for (int r = 0; r < 4; ++r) {
                    const int co = warpN * 32 + nt * 8 + 2 * tig + (r & 1);
                    const int xg = tx0 + gid + ((r & 2) ? 8 : 0);
                    const int vi = nt * 4 + r;
                    float z = acc[vi];
                    float vv = v[vi];
                    vv = vv + (z - vv) * 0.5f;   // TAU=2, reference op order
                    if (fabsf(vv - 1.0f) < FLAG_DELTA)
                        push_flag((((b * 64 + co) * 64 + yg) * 64) + xg);
                    float s = (vv >= 1.0f) ? 1.0f : 0.0f;
                    v[vi] = (vv >= 1.0f) ? 0.0f : vv;
                    obase[(size_t)co * 4096 + yg * 64 + xg] = s;
                }
            }

            __syncthreads();   // all MMA reads of input planes done

            // ---- commit prefetched inputs (convert + split + STS) ----
            if (t < TT - 1) {
                #pragma unroll
                for (int k = 0; k < PFN; ++k) {
                    int i   = tid + k * 256;
                    int ci  = i / 108;
                    int pix = i - ci * 108;
                    float val = pf[k];
                    __half h = __float2half_rn(val);
                    __half l = __float2half_rn(val - __half2float(h));
                    inhH[pix * 72 + ci] = h;
                    inlH[pix * 72 + ci] = l;
                }
                __syncthreads();
            }
        }
    }
}

// ---------------- flag-and-fix ----------------
// Warp-per-trajectory: exact fp64 conv (lane-split ci + shuffle reduce),
// round z to fp32, reference-identical fp32 LIF. Overwrites all T spikes.
// Last block resets g_cnt/g_done so the captured graph is replay-safe.
__global__ void fix_kernel(const float* __restrict__ x,
                           const float* __restrict__ w,
                           float* __restrict__ out)
{
    int n = g_cnt;
    if (n > FLAG_CAP) n = FLAG_CAP;
    const int lane = threadIdx.x & 31;
    const int wid  = (blockIdx.x * blockDim.x + threadIdx.x) >> 5;
    const int nw   = (gridDim.x * blockDim.x) >> 5;

    for (int i = wid; i < n; i += nw) {
        int e = g_idx[i];
        int xp = e & 63;
        int y  = (e >> 6) & 63;
        int co = (e >> 12) & 63;
        int b  = e >> 18;
        const float* wr = w + co * 576;
        const int ci0 = lane * 2;
        float v = 0.0f;
        for (int t = 0; t < TT; ++t) {
            const float* xt = x + (size_t)(t * BB + b) * (64 * 64 * 64);
            double z = 0.0;
            #pragma unroll
            for (int cc = 0; cc < 2; ++cc) {
                int ci = ci0 + cc;
                #pragma unroll
                for (int ky = 0; ky < 3; ++ky) {
                    int gy = y + ky - 1;
                    if ((unsigned)gy >= 64u) continue;
                    const float* xr = xt + ci * 4096 + gy * 64;
                    const float* wk = wr + ci * 9 + ky * 3;
                    #pragma unroll
                    for (int kx = 0; kx < 3; ++kx) {
                        int gx = xp + kx - 1;
                        if ((unsigned)gx >= 64u) continue;
                        z += (double)xr[gx] * (double)wk[kx];
                    }
                }
            }
            #pragma unroll
            for (int off = 16; off > 0; off >>= 1)
                z += __shfl_down_sync(0xffffffffu, z, off);
            if (lane == 0) {
                float zf = (float)z;
                v = v + (zf - v) * 0.5f;
                float s = (v >= 1.0f) ? 1.0f : 0.0f;
                v = (v >= 1.0f) ? 0.0f : v;
                out[((size_t)(t * BB + b) * 64 + co) * 4096 + y * 64 + xp] = s;
            }
        }
    }

    __syncthreads();
    if (threadIdx.x == 0) {
        __threadfence();
        int d = atomicAdd(&g_done, 1);
        if (d == (int)gridDim.x - 1) {
            g_cnt = 0;
            g_done = 0;
            __threadfence();
        }
    }
}

extern "C" void kernel_launch(void* const* d_in, const int* in_sizes, int n_in,
                              void* d_out, int out_size) {
    const float* x  = (const float*)d_in[0];
    const float* w  = (const float*)d_in[1];
    float* out      = (float*)d_out;
    cudaFuncSetAttribute(snn_conv_lif_kernel,
                         cudaFuncAttributeMaxDynamicSharedMemorySize, SMEM_BYTES);
    snn_conv_lif_kernel<<<NSM, 256, SMEM_BYTES>>>(x, w, out);
    fix_kernel<<<256, 256>>>(x, w, out);
}